// round 3
// baseline (speedup 1.0000x reference)
#include <cuda_runtime.h>
#include <cuda_bf16.h>
#include <cstdint>

#define Bsz 16
#define Ssz 64
#define Esz 256
#define Hsz 256
#define Msz (Bsz*Ssz)   /* 1024 flattened (b,s) rows */
#define G4H 1024        /* 4*H gate rows */

// ---------------------------------------------------------------------------
// Global scratch (no allocations allowed)
// ---------------------------------------------------------------------------
__device__ float g_emb[Msz*Esz];      // emb[b,s,:]            4 MB
__device__ float g_G1 [Msz*G4H];      // emb@W_ih^T + biases   4 MB
__device__ float g_Ex [Msz*G4H];      // emb@Wx^T + b_cell     4 MB
__device__ float g_shared[Msz*Hsz];   // pass-1 hidden states  1 MB
__device__ float g_A  [Msz*Hsz];      // shared@Ws1^T+emb@Ws3^T+Ws_b
__device__ float g_SWm[Msz*G4H];      // shared@Wm^T           4 MB

// ---------------------------------------------------------------------------
// Helpers
// ---------------------------------------------------------------------------
__device__ __forceinline__ float sigf(float x){ return 1.f/(1.f+__expf(-x)); }
__device__ __forceinline__ float tanha(float x){
  float r; asm("tanh.approx.f32 %0, %1;" : "=f"(r) : "f"(x)); return r;
}
__device__ __forceinline__ void cluster_sync_(){
  asm volatile("barrier.cluster.arrive.aligned;" ::: "memory");
  asm volatile("barrier.cluster.wait.aligned;"   ::: "memory");
}
// store one float into the same smem offset of cluster CTA `rk`
__device__ __forceinline__ void st_peer(void* lp, int rk, float v){
  uint32_t la = (uint32_t)__cvta_generic_to_shared(lp);
  uint32_t ra;
  asm volatile("mapa.shared::cluster.u32 %0, %1, %2;" : "=r"(ra) : "r"(la), "r"(rk));
  asm volatile("st.shared::cluster.f32 [%0], %1;" :: "r"(ra), "f"(v) : "memory");
}

// ---------------------------------------------------------------------------
// K0: embedding gather.  grid = 1024 blocks, 64 threads (one float4 each)
// ---------------------------------------------------------------------------
__global__ void k_gather(const int* __restrict__ x, const float* __restrict__ embed){
  int m = blockIdx.x;
  int v = x[m];
  const float4* s = (const float4*)(embed + (size_t)v*Esz);
  float4* d = (float4*)(g_emb + (size_t)m*Esz);
  d[threadIdx.x] = s[threadIdx.x];
}

// ---------------------------------------------------------------------------
// K1: generic tiled GEMM  C[m][n] = X[m]·W[n] (+bias1+bias2)
//   mode 0: G1 = emb@W_ih^T       (N=1024, K=256)
//   mode 1: Ex = emb@Wx^T         (N=1024, K=256)
//   mode 2: SWm = shared@Wm^T     (N=1024, K=256)
//   mode 3: A  = shared@Ws1^T + emb@Ws3^T  (N=256, K=512, Ksplit=256,
//               W row stride 768, cols >=Ksplit skip the middle 256 block)
// 64x64 tile, BK=16, 256 threads, 4x4 micro-tile.
// ---------------------------------------------------------------------------
__global__ void __launch_bounds__(256) k_gemm(
    int mode, const float* __restrict__ W, const float* __restrict__ b1,
    const float* __restrict__ b2, int N, int K, int Ksplit, int ldw, int wskip)
{
  const float* X1 = (mode >= 2) ? g_shared : g_emb;
  const float* X2 = g_emb;
  float* C = (mode==0) ? g_G1 : (mode==1) ? g_Ex : (mode==2) ? g_SWm : g_A;

  __shared__ __align__(16) float Xs[16][68];
  __shared__ __align__(16) float Ws[16][68];

  int tid = threadIdx.x;
  int m0 = blockIdx.x*64, n0 = blockIdx.y*64;
  int lr = tid>>2, lc = tid&3;          // load mapping
  int tx = tid&15, ty = tid>>4;         // compute mapping

  float acc[4][4];
  #pragma unroll
  for(int i=0;i<4;i++){
    #pragma unroll
    for(int j=0;j<4;j++) acc[i][j]=0.f;
  }

  for(int kt=0; kt<K; kt+=16){
    const float* xsrc = (kt < Ksplit)
        ? (X1 + (size_t)(m0+lr)*Esz + kt)
        : (X2 + (size_t)(m0+lr)*Esz + (kt-Ksplit));
    float4 xv = *(const float4*)(xsrc + lc*4);
    int kcol = kt + lc*4;
    int wc = (kcol < Ksplit) ? kcol : kcol + wskip;
    float4 wv = *(const float4*)(W + (size_t)(n0+lr)*ldw + wc);

    __syncthreads();   // previous iteration finished reading smem
    Xs[lc*4+0][lr]=xv.x; Xs[lc*4+1][lr]=xv.y; Xs[lc*4+2][lr]=xv.z; Xs[lc*4+3][lr]=xv.w;
    Ws[lc*4+0][lr]=wv.x; Ws[lc*4+1][lr]=wv.y; Ws[lc*4+2][lr]=wv.z; Ws[lc*4+3][lr]=wv.w;
    __syncthreads();

    #pragma unroll
    for(int k=0;k<16;k++){
      float4 a  = *(const float4*)&Xs[k][ty*4];
      float4 bb = *(const float4*)&Ws[k][tx*4];
      acc[0][0]+=a.x*bb.x; acc[0][1]+=a.x*bb.y; acc[0][2]+=a.x*bb.z; acc[0][3]+=a.x*bb.w;
      acc[1][0]+=a.y*bb.x; acc[1][1]+=a.y*bb.y; acc[1][2]+=a.y*bb.z; acc[1][3]+=a.y*bb.w;
      acc[2][0]+=a.z*bb.x; acc[2][1]+=a.z*bb.y; acc[2][2]+=a.z*bb.z; acc[2][3]+=a.z*bb.w;
      acc[3][0]+=a.w*bb.x; acc[3][1]+=a.w*bb.y; acc[3][2]+=a.w*bb.z; acc[3][3]+=a.w*bb.w;
    }
  }

  #pragma unroll
  for(int j=0;j<4;j++){
    int n = n0 + tx*4 + j;
    float bias = (b1 ? b1[n] : 0.f) + (b2 ? b2[n] : 0.f);
    #pragma unroll
    for(int i=0;i<4;i++)
      C[(size_t)(m0+ty*4+i)*N + n] = acc[i][j] + bias;
  }
}

// ---------------------------------------------------------------------------
// K2: pass-1 shared LSTM.  Cluster of 8 CTAs per batch element.
// CTA r owns h-indices [32r,32r+32) => 128 gate rows (4 gates x 32).
// Thread i: rq=i>>3 (h-index within slice), cc=i&7 (32-wide k-chunk).
// W_hh rows live in registers: w[gate][32]. Reduction over cc via shfl.
// h exchanged cluster-wide via DSMEM stores, double buffered, 1 sync/step.
// ---------------------------------------------------------------------------
__global__ void __cluster_dims__(8,1,1) __launch_bounds__(256,1)
k_pass1(const float* __restrict__ W_hh)
{
  __shared__ float sG1[Ssz*128];
  __shared__ float sh[2][Hsz];

  int b = blockIdx.x >> 3, r = blockIdx.x & 7;
  int tid = threadIdx.x;
  int rq = tid >> 3, cc = tid & 7;

  for(int idx=tid; idx<Ssz*128; idx+=256){
    int t = idx >> 7, lg = idx & 127;
    sG1[idx] = g_G1[(size_t)(b*Ssz+t)*G4H + (lg>>5)*Hsz + r*32 + (lg&31)];
  }
  float w[4][32];
  #pragma unroll
  for(int q=0;q<4;q++){
    const float4* src = (const float4*)(W_hh + (size_t)(q*Hsz + r*32 + rq)*Hsz + cc*32);
    #pragma unroll
    for(int kk=0;kk<8;kk++){
      float4 v = src[kk];
      w[q][kk*4+0]=v.x; w[q][kk*4+1]=v.y; w[q][kk*4+2]=v.z; w[q][kk*4+3]=v.w;
    }
  }
  sh[0][tid] = 0.f;
  float c = 0.f;
  __syncthreads();

  for(int t=0;t<Ssz;t++){
    const float* hk = sh[t&1] + cc*32;
    float a0=0.f,a1=0.f,a2=0.f,a3=0.f;
    #pragma unroll
    for(int k=0;k<32;k++){
      float hv = hk[k];
      a0 += w[0][k]*hv; a1 += w[1][k]*hv; a2 += w[2][k]*hv; a3 += w[3][k]*hv;
    }
    #pragma unroll
    for(int m=1;m<8;m<<=1){
      a0 += __shfl_xor_sync(0xffffffffu,a0,m);
      a1 += __shfl_xor_sync(0xffffffffu,a1,m);
      a2 += __shfl_xor_sync(0xffffffffu,a2,m);
      a3 += __shfl_xor_sync(0xffffffffu,a3,m);
    }
    if(cc==0){
      float gi = a0 + sG1[t*128 +      rq];
      float gf = a1 + sG1[t*128 + 32 + rq];
      float gg = a2 + sG1[t*128 + 64 + rq];
      float go = a3 + sG1[t*128 + 96 + rq];
      c = sigf(gf)*c + sigf(gi)*tanhf(gg);
      float h = sigf(go)*tanhf(c);
      int gidx = r*32 + rq;
      int p1 = (t+1)&1;
      #pragma unroll
      for(int rk=0;rk<8;rk++) st_peer(&sh[p1][gidx], rk, h);
      g_shared[(size_t)(b*Ssz+t)*Hsz + gidx] = h;
    }
    cluster_sync_();
  }
}

// ---------------------------------------------------------------------------
// K4: pass-2 task LSTM with attention.  Same cluster layout as K2.
// Per step: (a) hW2 = Ws2@h (exchange), (b) Si via tanh.approx (exchange),
// (c) softmax redundant in warp 0, (d) gates = Ex + Wh@h + att·SWm.
// Wh rows + Ws2 row + SWm slice in registers; 3 cluster syncs / step.
// ---------------------------------------------------------------------------
__global__ void __cluster_dims__(8,1,1) __launch_bounds__(256,1)
k_pass2(const float* __restrict__ Wh,   const float* __restrict__ Ws_w,
        const float* __restrict__ Us_w, const float* __restrict__ Us_b,
        const float* __restrict__ fc_w, const float* __restrict__ fc_b,
        const int*   __restrict__ mask, float* __restrict__ out)
{
  __shared__ float sEx[Ssz*128];
  __shared__ float sA[8*Hsz];
  __shared__ float sUs[Hsz];
  __shared__ float sh[2][Hsz];
  __shared__ float shW2[Hsz];
  __shared__ float sSi[Ssz];
  __shared__ float sAtt[Ssz];
  __shared__ int   sValid[Ssz];

  int b = blockIdx.x >> 3, r = blockIdx.x & 7;
  int tid = threadIdx.x;
  int rq = tid >> 3, cc = tid & 7;
  int lane = tid & 31, wid = tid >> 5;

  for(int idx=tid; idx<Ssz*128; idx+=256){
    int t = idx >> 7, lg = idx & 127;
    sEx[idx] = g_Ex[(size_t)(b*Ssz+t)*G4H + (lg>>5)*Hsz + r*32 + (lg&31)];
  }
  for(int idx=tid; idx<8*Hsz; idx+=256)
    sA[idx] = g_A[(size_t)(b*Ssz + r*8 + (idx>>8))*Hsz + (idx&255)];
  if(tid < Hsz) sUs[tid] = Us_w[tid];
  if(tid < Ssz) sValid[tid] = mask[b*Ssz + tid];
  sh[0][tid] = 0.f;

  float w[4][32];
  #pragma unroll
  for(int q=0;q<4;q++){
    const float4* src = (const float4*)(Wh + (size_t)(q*Hsz + r*32 + rq)*Hsz + cc*32);
    #pragma unroll
    for(int kk=0;kk<8;kk++){
      float4 v=src[kk];
      w[q][kk*4+0]=v.x; w[q][kk*4+1]=v.y; w[q][kk*4+2]=v.z; w[q][kk*4+3]=v.w;
    }
  }
  float sw2[32];
  {
    const float4* src = (const float4*)(Ws_w + (size_t)(r*32+rq)*768 + Hsz + cc*32);
    #pragma unroll
    for(int kk=0;kk<8;kk++){
      float4 v=src[kk];
      sw2[kk*4+0]=v.x; sw2[kk*4+1]=v.y; sw2[kk*4+2]=v.z; sw2[kk*4+3]=v.w;
    }
  }
  float sw[4][8];
  #pragma unroll
  for(int q=0;q<4;q++){
    #pragma unroll
    for(int ss=0;ss<8;ss++)
      sw[q][ss] = g_SWm[(size_t)(b*Ssz + cc*8 + ss)*G4H + q*Hsz + r*32 + rq];
  }
  float usb = Us_b[0];
  float c = 0.f;
  __syncthreads();

  for(int t=0;t<Ssz;t++){
    const float* hcur = sh[t&1];

    // (a) hW2[j] for this CTA's 32 j's
    {
      float p = 0.f;
      const float* hk = hcur + cc*32;
      #pragma unroll
      for(int k=0;k<32;k++) p += sw2[k]*hk[k];
      #pragma unroll
      for(int m=1;m<8;m<<=1) p += __shfl_xor_sync(0xffffffffu,p,m);
      if(cc==0){
        int j = r*32 + rq;
        #pragma unroll
        for(int rk=0;rk<8;rk++) st_peer(&shW2[j], rk, p);
      }
    }
    cluster_sync_();

    // (b) Si for this CTA's 8 s values (warp w -> s = 8r+w)
    {
      float sacc = 0.f;
      #pragma unroll
      for(int jj=0;jj<8;jj++){
        int j = jj*32 + lane;
        sacc += sUs[j]*tanha(sA[wid*Hsz + j] + shW2[j]);
      }
      #pragma unroll
      for(int m=16;m>=1;m>>=1) sacc += __shfl_xor_sync(0xffffffffu,sacc,m);
      if(lane==0){
        int s = r*8 + wid;
        float v = sacc + usb;
        #pragma unroll
        for(int rk=0;rk<8;rk++) st_peer(&sSi[s], rk, v);
      }
    }
    cluster_sync_();

    // (c) masked softmax over S (warp 0, redundant per CTA)
    if(wid==0){
      float v0 = sValid[lane]      ? sSi[lane]      : -1e9f;
      float v1 = sValid[lane+32]   ? sSi[lane+32]   : -1e9f;
      float mx = fmaxf(v0,v1);
      #pragma unroll
      for(int m=16;m>=1;m>>=1) mx = fmaxf(mx, __shfl_xor_sync(0xffffffffu,mx,m));
      float e0 = __expf(v0-mx), e1 = __expf(v1-mx);
      float sm = e0+e1;
      #pragma unroll
      for(int m=16;m>=1;m>>=1) sm += __shfl_xor_sync(0xffffffffu,sm,m);
      float inv = 1.f/sm;
      sAtt[lane]    = e0*inv;
      sAtt[lane+32] = e1*inv;
    }
    __syncthreads();

    // (d) gates = Ex + Wh@h + att·SWm
    {
      float av[8];
      #pragma unroll
      for(int ss=0;ss<8;ss++) av[ss] = sAtt[cc*8+ss];
      float a0=0.f,a1=0.f,a2=0.f,a3=0.f;
      #pragma unroll
      for(int ss=0;ss<8;ss++){
        a0 += sw[0][ss]*av[ss]; a1 += sw[1][ss]*av[ss];
        a2 += sw[2][ss]*av[ss]; a3 += sw[3][ss]*av[ss];
      }
      const float* hk = hcur + cc*32;
      #pragma unroll
      for(int k=0;k<32;k++){
        float hv = hk[k];
        a0 += w[0][k]*hv; a1 += w[1][k]*hv; a2 += w[2][k]*hv; a3 += w[3][k]*hv;
      }
      #pragma unroll
      for(int m=1;m<8;m<<=1){
        a0 += __shfl_xor_sync(0xffffffffu,a0,m);
        a1 += __shfl_xor_sync(0xffffffffu,a1,m);
        a2 += __shfl_xor_sync(0xffffffffu,a2,m);
        a3 += __shfl_xor_sync(0xffffffffu,a3,m);
      }
      if(cc==0){
        float gi = a0 + sEx[t*128 +      rq];
        float gf = a1 + sEx[t*128 + 32 + rq];
        float gg = a2 + sEx[t*128 + 64 + rq];
        float go = a3 + sEx[t*128 + 96 + rq];
        c = sigf(gf)*c + sigf(gi)*tanhf(gg);
        float h = sigf(go)*tanhf(c);
        int gidx = r*32 + rq;
        int p1 = (t+1)&1;
        #pragma unroll
        for(int rk=0;rk<8;rk++) st_peer(&sh[p1][gidx], rk, h);
      }
    }
    cluster_sync_();
  }

  // final classifier: out[b] = sigmoid(h·fc_w + fc_b)
  if(r==0 && wid==0){
    float acc = 0.f;
    #pragma unroll
    for(int jj=0;jj<8;jj++){ int j=jj*32+lane; acc += fc_w[j]*sh[0][j]; }
    #pragma unroll
    for(int m=16;m>=1;m>>=1) acc += __shfl_xor_sync(0xffffffffu,acc,m);
    if(lane==0) out[b] = sigf(acc + fc_b[0]);
  }
}

// ---------------------------------------------------------------------------
// Launch
// ---------------------------------------------------------------------------
extern "C" void kernel_launch(void* const* d_in, const int* in_sizes, int n_in,
                              void* d_out, int out_size)
{
  const int* x    = (const int*)d_in[0];
  const int* mask = (const int*)d_in[1];
  // TASK is a scalar int (size 1) if present; embed is 25.6M elements.
  int base = (in_sizes[2] == 1) ? 3 : 2;
  const float* embed  = (const float*)d_in[base+0];
  const float* W_ih   = (const float*)d_in[base+1];
  const float* W_hh   = (const float*)d_in[base+2];
  const float* b_ih   = (const float*)d_in[base+3];
  const float* b_hh   = (const float*)d_in[base+4];
  const float* Ws_w   = (const float*)d_in[base+5];
  const float* Ws_b   = (const float*)d_in[base+6];
  const float* Us_w   = (const float*)d_in[base+7];
  const float* Us_b   = (const float*)d_in[base+8];
  const float* Wx     = (const float*)d_in[base+9];
  const float* Wh     = (const float*)d_in[base+10];
  const float* Wm     = (const float*)d_in[base+11];
  const float* b_cell = (const float*)d_in[base+12];
  const float* fc_w   = (const float*)d_in[base+13];
  const float* fc_b   = (const float*)d_in[base+14];
  float* out = (float*)d_out;
  (void)n_in; (void)out_size;

  k_gather<<<Msz, 64>>>(x, embed);
  k_gemm<<<dim3(16,16), 256>>>(0, W_ih, b_ih, b_hh, G4H, 256, 256, 256, 0);
  k_gemm<<<dim3(16,16), 256>>>(1, Wx,   b_cell, nullptr, G4H, 256, 256, 256, 0);
  k_pass1<<<128, 256>>>(W_hh);
  k_gemm<<<dim3(16,16), 256>>>(2, Wm,   nullptr, nullptr, G4H, 256, 256, 256, 0);
  k_gemm<<<dim3(16,4),  256>>>(3, Ws_w, Ws_b,   nullptr, Hsz, 512, 256, 768, 256);
  k_pass2<<<128, 256>>>(Wh, Ws_w, Us_w, Us_b, fc_w, fc_b, mask, out);
}

// round 4
// speedup vs baseline: 1.2136x; 1.2136x over previous
#include <cuda_runtime.h>
#include <cuda_bf16.h>
#include <cstdint>

#define Bsz 16
#define Ssz 64
#define Esz 256
#define Hsz 256
#define Msz (Bsz*Ssz)   /* 1024 flattened (b,s) rows */
#define G4H 1024        /* 4*H gate rows */

// ---------------------------------------------------------------------------
// Global scratch (no allocations allowed)
// ---------------------------------------------------------------------------
__device__ float g_emb[Msz*Esz];      // emb[b,s,:]
__device__ float g_G1 [Msz*G4H];      // emb@W_ih^T + (b_ih+b_hh)
__device__ float g_Ex [Msz*G4H];      // emb@Wx^T + b_cell
__device__ float g_shared[Msz*Hsz];   // pass-1 hidden states
__device__ float g_A  [Msz*Hsz];      // shared@Ws1^T + emb@Ws3^T + Ws_b
__device__ float g_SWm[Msz*G4H];      // shared@Wm^T

// ---------------------------------------------------------------------------
// Helpers
// ---------------------------------------------------------------------------
__device__ __forceinline__ float sigf(float x){
  return __fdividef(1.f, 1.f + __expf(-x));
}
// accurate-enough fast tanh: rel err ~1e-6, clamped to avoid inf/inf
__device__ __forceinline__ float tanhfast(float x){
  float t = __expf(fminf(2.f*x, 80.f));
  return __fdividef(t - 1.f, t + 1.f);
}
__device__ __forceinline__ float tanha(float x){
  float r; asm("tanh.approx.f32 %0, %1;" : "=f"(r) : "f"(x)); return r;
}
__device__ __forceinline__ void cluster_sync_(){
  asm volatile("barrier.cluster.arrive.aligned;" ::: "memory");
  asm volatile("barrier.cluster.wait.aligned;"   ::: "memory");
}
// store one float into the same smem offset of cluster CTA `rk`
__device__ __forceinline__ void st_peer(void* lp, int rk, float v){
  uint32_t la = (uint32_t)__cvta_generic_to_shared(lp);
  uint32_t ra;
  asm volatile("mapa.shared::cluster.u32 %0, %1, %2;" : "=r"(ra) : "r"(la), "r"(rk));
  asm volatile("st.shared::cluster.f32 [%0], %1;" :: "r"(ra), "f"(v) : "memory");
}

// ---------------------------------------------------------------------------
// K0: embedding gather.  grid = 1024 blocks, 64 threads (one float4 each)
// ---------------------------------------------------------------------------
__global__ void k_gather(const int* __restrict__ x, const float* __restrict__ embed){
  int m = blockIdx.x;
  int v = x[m];
  const float4* s = (const float4*)(embed + (size_t)v*Esz);
  float4* d = (float4*)(g_emb + (size_t)m*Esz);
  d[threadIdx.x] = s[threadIdx.x];
}

// ---------------------------------------------------------------------------
// K1: generic tiled GEMM  C[m][n] = X[m]·W[n] (+bias1+bias2)
//   mode 0: G1 = emb@W_ih^T       mode 1: Ex = emb@Wx^T
//   mode 2: SWm = shared@Wm^T     mode 3: A = shared@Ws1^T + emb@Ws3^T
// 64x64 tile, BK=16, 256 threads, 4x4 micro-tile.
// ---------------------------------------------------------------------------
__global__ void __launch_bounds__(256) k_gemm(
    int mode, const float* __restrict__ W, const float* __restrict__ b1,
    const float* __restrict__ b2, int N, int K, int Ksplit, int ldw, int wskip)
{
  const float* X1 = (mode >= 2) ? g_shared : g_emb;
  const float* X2 = g_emb;
  float* C = (mode==0) ? g_G1 : (mode==1) ? g_Ex : (mode==2) ? g_SWm : g_A;

  __shared__ __align__(16) float Xs[16][68];
  __shared__ __align__(16) float Ws[16][68];

  int tid = threadIdx.x;
  int m0 = blockIdx.x*64, n0 = blockIdx.y*64;
  int lr = tid>>2, lc = tid&3;          // load mapping
  int tx = tid&15, ty = tid>>4;         // compute mapping

  float acc[4][4];
  #pragma unroll
  for(int i=0;i<4;i++){
    #pragma unroll
    for(int j=0;j<4;j++) acc[i][j]=0.f;
  }

  for(int kt=0; kt<K; kt+=16){
    const float* xsrc = (kt < Ksplit)
        ? (X1 + (size_t)(m0+lr)*Esz + kt)
        : (X2 + (size_t)(m0+lr)*Esz + (kt-Ksplit));
    float4 xv = *(const float4*)(xsrc + lc*4);
    int kcol = kt + lc*4;
    int wc = (kcol < Ksplit) ? kcol : kcol + wskip;
    float4 wv = *(const float4*)(W + (size_t)(n0+lr)*ldw + wc);

    __syncthreads();
    Xs[lc*4+0][lr]=xv.x; Xs[lc*4+1][lr]=xv.y; Xs[lc*4+2][lr]=xv.z; Xs[lc*4+3][lr]=xv.w;
    Ws[lc*4+0][lr]=wv.x; Ws[lc*4+1][lr]=wv.y; Ws[lc*4+2][lr]=wv.z; Ws[lc*4+3][lr]=wv.w;
    __syncthreads();

    #pragma unroll
    for(int k=0;k<16;k++){
      float4 a  = *(const float4*)&Xs[k][ty*4];
      float4 bb = *(const float4*)&Ws[k][tx*4];
      acc[0][0]+=a.x*bb.x; acc[0][1]+=a.x*bb.y; acc[0][2]+=a.x*bb.z; acc[0][3]+=a.x*bb.w;
      acc[1][0]+=a.y*bb.x; acc[1][1]+=a.y*bb.y; acc[1][2]+=a.y*bb.z; acc[1][3]+=a.y*bb.w;
      acc[2][0]+=a.z*bb.x; acc[2][1]+=a.z*bb.y; acc[2][2]+=a.z*bb.z; acc[2][3]+=a.z*bb.w;
      acc[3][0]+=a.w*bb.x; acc[3][1]+=a.w*bb.y; acc[3][2]+=a.w*bb.z; acc[3][3]+=a.w*bb.w;
    }
  }

  #pragma unroll
  for(int j=0;j<4;j++){
    int n = n0 + tx*4 + j;
    float bias = (b1 ? b1[n] : 0.f) + (b2 ? b2[n] : 0.f);
    #pragma unroll
    for(int i=0;i<4;i++)
      C[(size_t)(m0+ty*4+i)*N + n] = acc[i][j] + bias;
  }
}

// ---------------------------------------------------------------------------
// K2: pass-1 shared LSTM.  Cluster of 8 CTAs per batch element, 512 threads.
// CTA r owns h-indices [32r,32r+32) => 128 gate rows.
// Thread: rq = tid>>4 (row in slice), cc = tid&15 (16-wide k-chunk).
// W_hh rows in registers: w[4][16] = 64 regs/thread (no spills).
// G1 gate terms prefetched per step via LDG (L2-resident, latency hidden).
// ---------------------------------------------------------------------------
__global__ void __cluster_dims__(8,1,1) __launch_bounds__(512,1)
k_pass1(const float* __restrict__ W_hh)
{
  __shared__ float sh[2][Hsz];

  int b = blockIdx.x >> 3, r = blockIdx.x & 7;
  int tid = threadIdx.x;
  int rq = tid >> 4, cc = tid & 15;
  int gidx = r*32 + rq;

  float w[4][16];
  #pragma unroll
  for(int q=0;q<4;q++){
    const float4* src = (const float4*)(W_hh + (size_t)(q*Hsz + gidx)*Hsz + cc*16);
    #pragma unroll
    for(int kk=0;kk<4;kk++){
      float4 v = src[kk];
      w[q][kk*4+0]=v.x; w[q][kk*4+1]=v.y; w[q][kk*4+2]=v.z; w[q][kk*4+3]=v.w;
    }
  }
  if(tid < Hsz) sh[0][tid] = 0.f;
  float c = 0.f;
  __syncthreads();
  cluster_sync_();   // peers' sh[0] initialized before anyone reads it

  const float* __restrict__ G1b = g_G1 + (size_t)b*Ssz*G4H + gidx;

  for(int t=0;t<Ssz;t++){
    // prefetch this step's gate-input terms (consumed after the reduction)
    float e0,e1,e2,e3;
    if(cc==0){
      const float* p = G1b + (size_t)t*G4H;
      e0 = p[0]; e1 = p[256]; e2 = p[512]; e3 = p[768];
    }
    const float* hk = sh[t&1] + cc*16;
    float a0=0.f,a1=0.f,a2=0.f,a3=0.f;
    #pragma unroll
    for(int k=0;k<16;k++){
      float hv = hk[k];
      a0 += w[0][k]*hv; a1 += w[1][k]*hv; a2 += w[2][k]*hv; a3 += w[3][k]*hv;
    }
    #pragma unroll
    for(int m=1;m<16;m<<=1){
      a0 += __shfl_xor_sync(0xffffffffu,a0,m);
      a1 += __shfl_xor_sync(0xffffffffu,a1,m);
      a2 += __shfl_xor_sync(0xffffffffu,a2,m);
      a3 += __shfl_xor_sync(0xffffffffu,a3,m);
    }
    if(cc==0){
      float gi = a0 + e0, gf = a1 + e1, gg = a2 + e2, go = a3 + e3;
      c = sigf(gf)*c + sigf(gi)*tanhfast(gg);
      float h = sigf(go)*tanhfast(c);
      int p1 = (t+1)&1;
      #pragma unroll
      for(int rk=0;rk<8;rk++) st_peer(&sh[p1][gidx], rk, h);
      g_shared[(size_t)(b*Ssz+t)*Hsz + gidx] = h;
    }
    cluster_sync_();
  }
}

// ---------------------------------------------------------------------------
// K4: pass-2 task LSTM with attention.  Cluster 8, 512 threads.
// Per step: (pre) both Ws2·h and Wh·h dots, exchange hW2 [sync1];
//           Si via tanh.approx, exchange [sync2];
//           softmax local, att·SWm + gates, exchange h [sync3].
// Wh + Ws2 slices in registers (80 floats); SWm slice in smem [row][64]
// read via LDS.128 (conflict-free). Ex prefetched per step via LDG.
// ---------------------------------------------------------------------------
__global__ void __cluster_dims__(8,1,1) __launch_bounds__(512,1)
k_pass2(const float* __restrict__ Wh,   const float* __restrict__ Ws_w,
        const float* __restrict__ Us_w, const float* __restrict__ Us_b,
        const float* __restrict__ fc_w, const float* __restrict__ fc_b,
        const int*   __restrict__ mask, float* __restrict__ out)
{
  __shared__ __align__(16) float sSWm[128*64];  // [q*32+rq][s]  32 KB
  __shared__ float sA[8*Hsz];                   // 8 s rows of A  8 KB
  __shared__ float sUs[Hsz];
  __shared__ float sh[2][Hsz];
  __shared__ float shW2[Hsz];
  __shared__ float sSi[Ssz];
  __shared__ float sAtt[Ssz];
  __shared__ int   sValid[Ssz];

  int b = blockIdx.x >> 3, r = blockIdx.x & 7;
  int tid = threadIdx.x;
  int rq = tid >> 4, cc = tid & 15;
  int lane = tid & 31, wid = tid >> 5;
  int gidx = r*32 + rq;

  // prologue loads
  for(int idx=tid; idx<128*64; idx+=512){
    int row = idx >> 6, s = idx & 63;   // row = q*32+rq_l
    sSWm[idx] = g_SWm[(size_t)(b*Ssz+s)*G4H + (row>>5)*Hsz + r*32 + (row&31)];
  }
  for(int idx=tid; idx<8*Hsz; idx+=512)
    sA[idx] = g_A[(size_t)(b*Ssz + r*8 + (idx>>8))*Hsz + (idx&255)];
  if(tid < Hsz) sUs[tid] = Us_w[tid];
  if(tid < Ssz) sValid[tid] = mask[b*Ssz + tid];
  if(tid < Hsz) sh[0][tid] = 0.f;

  float w[4][16];
  #pragma unroll
  for(int q=0;q<4;q++){
    const float4* src = (const float4*)(Wh + (size_t)(q*Hsz + gidx)*Hsz + cc*16);
    #pragma unroll
    for(int kk=0;kk<4;kk++){
      float4 v=src[kk];
      w[q][kk*4+0]=v.x; w[q][kk*4+1]=v.y; w[q][kk*4+2]=v.z; w[q][kk*4+3]=v.w;
    }
  }
  float sw2[16];
  {
    const float4* src = (const float4*)(Ws_w + (size_t)gidx*768 + Hsz + cc*16);
    #pragma unroll
    for(int kk=0;kk<4;kk++){
      float4 v=src[kk];
      sw2[kk*4+0]=v.x; sw2[kk*4+1]=v.y; sw2[kk*4+2]=v.z; sw2[kk*4+3]=v.w;
    }
  }
  float usb = Us_b[0];
  float c = 0.f;
  __syncthreads();
  cluster_sync_();   // peers' sh[0] initialized

  const float* __restrict__ Exb = g_Ex + (size_t)b*Ssz*G4H + gidx;

  for(int t=0;t<Ssz;t++){
    // prefetch Ex gate terms for this step
    float e0,e1,e2,e3;
    if(cc==0){
      const float* p = Exb + (size_t)t*G4H;
      e0 = p[0]; e1 = p[256]; e2 = p[512]; e3 = p[768];
    }

    // (pre) both dot products against current h
    const float* hk = sh[t&1] + cc*16;
    float pw=0.f, a0=0.f,a1=0.f,a2=0.f,a3=0.f;
    #pragma unroll
    for(int k=0;k<16;k++){
      float hv = hk[k];
      pw += sw2[k]*hv;
      a0 += w[0][k]*hv; a1 += w[1][k]*hv; a2 += w[2][k]*hv; a3 += w[3][k]*hv;
    }
    #pragma unroll
    for(int m=1;m<16;m<<=1){
      pw += __shfl_xor_sync(0xffffffffu,pw,m);
      a0 += __shfl_xor_sync(0xffffffffu,a0,m);
      a1 += __shfl_xor_sync(0xffffffffu,a1,m);
      a2 += __shfl_xor_sync(0xffffffffu,a2,m);
      a3 += __shfl_xor_sync(0xffffffffu,a3,m);
    }
    if(cc==0){
      #pragma unroll
      for(int rk=0;rk<8;rk++) st_peer(&shW2[gidx], rk, pw);
    }
    cluster_sync_();

    // (b) Si for this CTA's 8 s values (warps 0-7)
    if(wid < 8){
      float sacc = 0.f;
      #pragma unroll
      for(int jj=0;jj<8;jj++){
        int j = jj*32 + lane;
        sacc += sUs[j]*tanha(sA[wid*Hsz + j] + shW2[j]);
      }
      #pragma unroll
      for(int m=16;m>=1;m>>=1) sacc += __shfl_xor_sync(0xffffffffu,sacc,m);
      if(lane==0){
        int s = r*8 + wid;
        float v = sacc + usb;
        #pragma unroll
        for(int rk=0;rk<8;rk++) st_peer(&sSi[s], rk, v);
      }
    }
    cluster_sync_();

    // (c) masked softmax over S (warp 0, redundant per CTA)
    if(wid==0){
      float v0 = sValid[lane]    ? sSi[lane]    : -1e9f;
      float v1 = sValid[lane+32] ? sSi[lane+32] : -1e9f;
      float mx = fmaxf(v0,v1);
      #pragma unroll
      for(int m=16;m>=1;m>>=1) mx = fmaxf(mx, __shfl_xor_sync(0xffffffffu,mx,m));
      float x0 = __expf(v0-mx), x1 = __expf(v1-mx);
      float sm = x0+x1;
      #pragma unroll
      for(int m=16;m>=1;m>>=1) sm += __shfl_xor_sync(0xffffffffu,sm,m);
      float inv = __fdividef(1.f, sm);
      sAtt[lane]    = x0*inv;
      sAtt[lane+32] = x1*inv;
    }
    __syncthreads();

    // (d) att·SWm (each thread: 4 s values, LDS.128 per gate) + gates
    {
      const float4 av = *(const float4*)&sAtt[cc*4];
      float b0,b1,b2,b3;
      {
        float4 v = *(const float4*)&sSWm[(0*32+rq)*64 + cc*4];
        b0 = v.x*av.x + v.y*av.y + v.z*av.z + v.w*av.w;
      }
      {
        float4 v = *(const float4*)&sSWm[(1*32+rq)*64 + cc*4];
        b1 = v.x*av.x + v.y*av.y + v.z*av.z + v.w*av.w;
      }
      {
        float4 v = *(const float4*)&sSWm[(2*32+rq)*64 + cc*4];
        b2 = v.x*av.x + v.y*av.y + v.z*av.z + v.w*av.w;
      }
      {
        float4 v = *(const float4*)&sSWm[(3*32+rq)*64 + cc*4];
        b3 = v.x*av.x + v.y*av.y + v.z*av.z + v.w*av.w;
      }
      #pragma unroll
      for(int m=1;m<16;m<<=1){
        b0 += __shfl_xor_sync(0xffffffffu,b0,m);
        b1 += __shfl_xor_sync(0xffffffffu,b1,m);
        b2 += __shfl_xor_sync(0xffffffffu,b2,m);
        b3 += __shfl_xor_sync(0xffffffffu,b3,m);
      }
      if(cc==0){
        float gi = a0 + b0 + e0;
        float gf = a1 + b1 + e1;
        float gg = a2 + b2 + e2;
        float go = a3 + b3 + e3;
        c = sigf(gf)*c + sigf(gi)*tanhfast(gg);
        float h = sigf(go)*tanhfast(c);
        int p1 = (t+1)&1;
        #pragma unroll
        for(int rk=0;rk<8;rk++) st_peer(&sh[p1][gidx], rk, h);
      }
    }
    cluster_sync_();
  }

  // final classifier: out[b] = sigmoid(h·fc_w + fc_b)
  if(r==0 && wid==0){
    float acc = 0.f;
    #pragma unroll
    for(int jj=0;jj<8;jj++){ int j=jj*32+lane; acc += fc_w[j]*sh[0][j]; }
    #pragma unroll
    for(int m=16;m>=1;m>>=1) acc += __shfl_xor_sync(0xffffffffu,acc,m);
    if(lane==0) out[b] = sigf(acc + fc_b[0]);
  }
}

// ---------------------------------------------------------------------------
// Launch
// ---------------------------------------------------------------------------
extern "C" void kernel_launch(void* const* d_in, const int* in_sizes, int n_in,
                              void* d_out, int out_size)
{
  const int* x    = (const int*)d_in[0];
  const int* mask = (const int*)d_in[1];
  int base = (in_sizes[2] == 1) ? 3 : 2;   // skip scalar TASK if present
  const float* embed  = (const float*)d_in[base+0];
  const float* W_ih   = (const float*)d_in[base+1];
  const float* W_hh   = (const float*)d_in[base+2];
  const float* b_ih   = (const float*)d_in[base+3];
  const float* b_hh   = (const float*)d_in[base+4];
  const float* Ws_w   = (const float*)d_in[base+5];
  const float* Ws_b   = (const float*)d_in[base+6];
  const float* Us_w   = (const float*)d_in[base+7];
  const float* Us_b   = (const float*)d_in[base+8];
  const float* Wx     = (const float*)d_in[base+9];
  const float* Wh     = (const float*)d_in[base+10];
  const float* Wm     = (const float*)d_in[base+11];
  const float* b_cell = (const float*)d_in[base+12];
  const float* fc_w   = (const float*)d_in[base+13];
  const float* fc_b   = (const float*)d_in[base+14];
  float* out = (float*)d_out;
  (void)n_in; (void)out_size;

  k_gather<<<Msz, 64>>>(x, embed);
  k_gemm<<<dim3(16,16), 256>>>(0, W_ih, b_ih, b_hh, G4H, 256, 256, 256, 0);
  k_gemm<<<dim3(16,16), 256>>>(1, Wx,   b_cell, nullptr, G4H, 256, 256, 256, 0);
  k_pass1<<<128, 512>>>(W_hh);
  k_gemm<<<dim3(16,16), 256>>>(2, Wm,   nullptr, nullptr, G4H, 256, 256, 256, 0);
  k_gemm<<<dim3(16,4),  256>>>(3, Ws_w, Ws_b,   nullptr, Hsz, 512, 256, 768, 256);
  k_pass2<<<128, 512>>>(Wh, Ws_w, Us_w, Us_b, fc_w, fc_b, mask, out);
}